// round 9
// baseline (speedup 1.0000x reference)
#include <cuda_runtime.h>
#include <cuda_fp16.h>
#include <cstdint>

#define B_SZ 8192
#define L_SZ 64
#define EMB  64
#define HID  128
#define G3   384
#define OUTD 128
#define NVAL 1000

__device__ float g_tab[NVAL * G3];      // xg table, PERMUTED within 16-chunks (fp32, L2-hot)
__device__ float g_Wih_t[EMB * G3];
__device__ float g_cbias[G3];
__device__ uint32_t g_Bf[8 * 8 * 32 * 12];  // Whh fp16 B-fragments, 96KB
__device__ uint32_t g_Of[8 * 32 * 32];      // Wout fp16 B-fragments, 32KB

__device__ __forceinline__ float ftanh_fast(float x) {
    float r;
    asm("tanh.approx.f32 %0, %1;" : "=f"(r) : "f"(x));
    return r;
}
__device__ __forceinline__ float fsig_fast(float x) {
    return fmaf(0.5f, ftanh_fast(0.5f * x), 0.5f);
}
__device__ __forceinline__ uint32_t packh2(float lo, float hi) {
    __half2 h = __floats2half2_rn(lo, hi);
    return *reinterpret_cast<uint32_t*>(&h);
}
__device__ __forceinline__ void hmma(float* d, const uint32_t* a, uint32_t b0, uint32_t b1) {
    asm volatile("mma.sync.aligned.m16n8k16.row.col.f32.f16.f16.f32 "
        "{%0,%1,%2,%3}, {%4,%5,%6,%7}, {%8,%9}, {%0,%1,%2,%3};"
        : "+f"(d[0]), "+f"(d[1]), "+f"(d[2]), "+f"(d[3])
        : "r"(a[0]), "r"(a[1]), "r"(a[2]), "r"(a[3]), "r"(b0), "r"(b1));
}
__device__ __forceinline__ int pperm(int o) {
    return 4 * ((o & 7) >> 1) + (((o >> 3) & 1) << 1) + (o & 1);
}

// ---------------- prep: fragment images ----------------
__global__ void prep_kernel(const float* __restrict__ Wih, const float* __restrict__ Whh,
                            const float* __restrict__ bih, const float* __restrict__ bhh,
                            const float* __restrict__ Wout) {
    int i = blockIdx.x * blockDim.x + threadIdx.x;
    if (i < EMB * G3) { int k = i / G3, gj = i % G3; g_Wih_t[i] = Wih[gj * EMB + k]; }
    if (i < G3) g_cbias[i] = bih[i] + (i < 2 * HID ? bhh[i] : 0.0f);
    if (i < G3 * HID) {
        int gj = i / HID, k = i % HID;
        uint16_t hb = __half_as_ushort(__float2half_rn(Whh[i]));
        int gate = gj >> 7, jr = gj & 127;
        int jc = jr >> 4, nt = (jr >> 3) & 1, nl = jr & 7;
        int kc = k >> 4, kk = k & 15;
        int breg = kk >> 3, q = (kk & 7) >> 1, hs = kk & 1;
        int T = nl * 4 + q, f = gate * 2 + nt;
        int u = ((jc * 8 + kc) * 32 + T) * 12 + f * 2 + breg;
        ((uint16_t*)g_Bf)[u * 2 + hs] = hb;
    }
    if (i < OUTD * HID) {
        int o = i / HID, k = i % HID;
        uint16_t hb = __half_as_ushort(__float2half_rn(Wout[i]));
        int f = o >> 3, nl = o & 7;
        int kc = k >> 4, kk = k & 15;
        int breg = kk >> 3, q = (kk & 7) >> 1, hs = kk & 1;
        int T = nl * 4 + q;
        int u = (kc * 32 + T) * 32 + f * 2 + breg;
        ((uint16_t*)g_Of)[u * 2 + hs] = hb;
    }
}

__global__ void table_kernel(const float* __restrict__ embed) {
    __shared__ float es[EMB];
    const int v = blockIdx.x, gj = threadIdx.x;
    if (gj < EMB) es[gj] = embed[v * EMB + gj];
    __syncthreads();
    float acc = 0.0f;
    #pragma unroll 8
    for (int k = 0; k < EMB; k++) acc = fmaf(es[k], g_Wih_t[k * G3 + gj], acc);
    const int gate = gj >> 7, rest = gj & 127, chunk = rest >> 4, o = rest & 15;
    g_tab[v * G3 + gate * 128 + chunk * 16 + pperm(o)] = acc + g_cbias[gj];
}

// ---------------- GRU: phase-rotated warps, pipelined xg loads, folded d-init ----------------
#define GRU_SMEM (131072 + 512)
__global__ __launch_bounds__(128, 1) void gru_kernel(const int* __restrict__ x,
                                                     const float* __restrict__ bhh,
                                                     const float* __restrict__ bout,
                                                     float* __restrict__ out) {
    extern __shared__ uint32_t sm[];
    uint32_t* Bs = sm;                      // 24576 u32
    uint32_t* Os = sm + 24576;              // 8192 u32
    float* bns = (float*)(sm + 32768);      // 128 floats, permuted bhh_n
    const int tid = threadIdx.x;
    {
        uint4* d = (uint4*)sm;
        const uint4* s1 = (const uint4*)g_Bf;
        for (int i = tid; i < 6144; i += 128) d[i] = s1[i];
        const uint4* s2 = (const uint4*)g_Of;
        for (int i = tid; i < 2048; i += 128) d[6144 + i] = s2[i];
    }
    if (tid < 128) {
        int o = tid & 15, chunk = tid >> 4;
        bns[chunk * 16 + pperm(o)] = bhh[256 + tid];
    }
    __syncthreads();

    const int w = tid >> 5, T = tid & 31;
    const int g = T >> 2, a4 = (T & 3) * 4;
    const int jc0 = (w * 2) & 7;            // per-warp phase rotation
    const int rowA = blockIdx.x * 64 + w * 16 + g;
    const int rowB = rowA + 8;
    const float* __restrict__ tab = g_tab;

    uint32_t A[32], An[32];
    float hp[64];
    #pragma unroll
    for (int i = 0; i < 32; i++) A[i] = 0u;
    #pragma unroll
    for (int i = 0; i < 64; i++) hp[i] = 0.0f;

    int idxA = x[rowA * L_SZ], idxB = x[rowB * L_SZ];
    const float* tA = tab + (size_t)idxA * G3 + a4;
    const float* tB = tab + (size_t)idxB * G3 + a4;

    // preload first chunk of step 0
    float4 crA = __ldg((const float4*)(tA + jc0 * 16));
    float4 crB = __ldg((const float4*)(tB + jc0 * 16));
    float4 czA = __ldg((const float4*)(tA + 128 + jc0 * 16));
    float4 czB = __ldg((const float4*)(tB + 128 + jc0 * 16));
    float4 cnA = __ldg((const float4*)(tA + 256 + jc0 * 16));
    float4 cnB = __ldg((const float4*)(tB + 256 + jc0 * 16));

    #pragma unroll 1
    for (int t = 0; t < L_SZ; t++) {
        int idxA2 = idxA, idxB2 = idxB;
        if (t + 1 < L_SZ) {
            idxA2 = x[rowA * L_SZ + t + 1];
            idxB2 = x[rowB * L_SZ + t + 1];
        }
        #pragma unroll
        for (int jci = 0; jci < 8; jci++) {
            const int jcr = (jc0 + jci) & 7;
            float4 bn4 = *(const float4*)(bns + jcr * 16 + a4);

            // accumulators pre-loaded with gate offsets (folds epilogue adds)
            float d[6][4] = {
                {crA.x, crA.y, crB.x, crB.y}, {crA.z, crA.w, crB.z, crB.w},
                {czA.x, czA.y, czB.x, czB.y}, {czA.z, czA.w, czB.z, czB.w},
                {bn4.x, bn4.y, bn4.x, bn4.y}, {bn4.z, bn4.w, bn4.z, bn4.w}
            };

            // pipeline: issue next chunk's xg loads (hidden under the HMMAs)
            float4 nrA, nrB, nzA, nzB, nnA, nnB;
            if (jci < 7) {
                const int jn = ((jc0 + jci + 1) & 7) * 16;
                nrA = __ldg((const float4*)(tA + jn));
                nrB = __ldg((const float4*)(tB + jn));
                nzA = __ldg((const float4*)(tA + 128 + jn));
                nzB = __ldg((const float4*)(tB + 128 + jn));
                nnA = __ldg((const float4*)(tA + 256 + jn));
                nnB = __ldg((const float4*)(tB + 256 + jn));
            } else {
                tA = tab + (size_t)idxA2 * G3 + a4;
                tB = tab + (size_t)idxB2 * G3 + a4;
                nrA = __ldg((const float4*)(tA + jc0 * 16));
                nrB = __ldg((const float4*)(tB + jc0 * 16));
                nzA = __ldg((const float4*)(tA + 128 + jc0 * 16));
                nzB = __ldg((const float4*)(tB + 128 + jc0 * 16));
                nnA = __ldg((const float4*)(tA + 256 + jc0 * 16));
                nnB = __ldg((const float4*)(tB + 256 + jc0 * 16));
            }

            #pragma unroll
            for (int kc = 0; kc < 8; kc++) {
                const uint4* bp = (const uint4*)(Bs + ((jcr * 8 + kc) * 32 + T) * 12);
                uint4 b0 = bp[0], b1 = bp[1], b2 = bp[2];
                hmma(d[0], &A[kc * 4], b0.x, b0.y);
                hmma(d[1], &A[kc * 4], b0.z, b0.w);
                hmma(d[2], &A[kc * 4], b1.x, b1.y);
                hmma(d[3], &A[kc * 4], b1.z, b1.w);
                hmma(d[4], &A[kc * 4], b2.x, b2.y);
                hmma(d[5], &A[kc * 4], b2.z, b2.w);
            }

            float xn[8] = {cnA.x, cnA.y, cnB.x, cnB.y, cnA.z, cnA.w, cnB.z, cnB.w};
            float hv[8];
            #pragma unroll
            for (int u = 0; u < 8; u++) {
                int nt = u >> 2, pos = u & 3;
                float r = fsig_fast(d[nt][pos]);
                float z = fsig_fast(d[2 + nt][pos]);
                float n = ftanh_fast(fmaf(r, d[4 + nt][pos], xn[u]));
                float h = fmaf(z, hp[jcr * 8 + u] - n, n);
                hp[jcr * 8 + u] = h;
                hv[u] = h;
            }
            An[jcr * 4 + 0] = packh2(hv[0], hv[1]);
            An[jcr * 4 + 1] = packh2(hv[2], hv[3]);
            An[jcr * 4 + 2] = packh2(hv[4], hv[5]);
            An[jcr * 4 + 3] = packh2(hv[6], hv[7]);

            crA = nrA; crB = nrB; czA = nzA; czB = nzB; cnA = nnA; cnB = nnB;
        }
        #pragma unroll
        for (int i = 0; i < 32; i++) A[i] = An[i];
        idxA = idxA2; idxB = idxB2;
    }

    // output projection: out = h @ Wout^T + bout
    float od[16][4];
    #pragma unroll
    for (int f = 0; f < 16; f++)
        #pragma unroll
        for (int p = 0; p < 4; p++) od[f][p] = 0.0f;
    #pragma unroll
    for (int kc = 0; kc < 8; kc++) {
        const uint4* op = (const uint4*)(Os + (kc * 32 + T) * 32);
        #pragma unroll
        for (int f2 = 0; f2 < 8; f2++) {
            uint4 v = op[f2];
            hmma(od[f2 * 2 + 0], &A[kc * 4], v.x, v.y);
            hmma(od[f2 * 2 + 1], &A[kc * 4], v.z, v.w);
        }
    }
    const int q2 = (T & 3) * 2;
    #pragma unroll
    for (int f = 0; f < 16; f++) {
        float2 bo = *(const float2*)(bout + f * 8 + q2);
        float2 oA = make_float2(od[f][0] + bo.x, od[f][1] + bo.y);
        float2 oB = make_float2(od[f][2] + bo.x, od[f][3] + bo.y);
        *(float2*)(out + (size_t)rowA * OUTD + f * 8 + q2) = oA;
        *(float2*)(out + (size_t)rowB * OUTD + f * 8 + q2) = oB;
    }
}

extern "C" void kernel_launch(void* const* d_in, const int* in_sizes, int n_in,
                              void* d_out, int out_size) {
    const int*   x     = (const int*)d_in[0];
    const float* embed = (const float*)d_in[1];
    const float* Wih   = (const float*)d_in[2];
    const float* Whh   = (const float*)d_in[3];
    const float* bih   = (const float*)d_in[4];
    const float* bhh   = (const float*)d_in[5];
    const float* Wout  = (const float*)d_in[6];
    const float* bout  = (const float*)d_in[7];
    float* out = (float*)d_out;

    static bool attr_done = false;
    if (!attr_done) {
        cudaFuncSetAttribute(gru_kernel, cudaFuncAttributeMaxDynamicSharedMemorySize, GRU_SMEM);
        attr_done = true;
    }

    prep_kernel<<<192, 256>>>(Wih, Whh, bih, bhh, Wout);
    table_kernel<<<NVAL, G3>>>(embed);
    gru_kernel<<<B_SZ / 64, 128, GRU_SMEM>>>(x, bhh, bout, out);
}

// round 10
// speedup vs baseline: 1.0836x; 1.0836x over previous
#include <cuda_runtime.h>
#include <cuda_fp16.h>
#include <cstdint>

#define B_SZ 8192
#define L_SZ 64
#define EMB  64
#define HID  128
#define G3   384
#define OUTD 128
#define NVAL 1000

__device__ float g_tab[NVAL * G3];      // xg table, PERMUTED within 16-chunks (fp32, L2-hot)
__device__ float g_Wih_t[EMB * G3];
__device__ float g_cbias[G3];
__device__ uint32_t g_Bf[8 * 8 * 32 * 12];  // Whh fp16 B-fragments, 96KB
__device__ uint32_t g_Of[8 * 32 * 32];      // Wout fp16 B-fragments, 32KB

__device__ __forceinline__ float ftanh_fast(float x) {
    float r;
    asm("tanh.approx.f32 %0, %1;" : "=f"(r) : "f"(x));
    return r;
}
__device__ __forceinline__ float fsig_fast(float x) {
    return fmaf(0.5f, ftanh_fast(0.5f * x), 0.5f);
}
__device__ __forceinline__ uint32_t packh2(float lo, float hi) {
    __half2 h = __floats2half2_rn(lo, hi);
    return *reinterpret_cast<uint32_t*>(&h);
}
__device__ __forceinline__ void hmma(float* d, const uint32_t* a, uint32_t b0, uint32_t b1) {
    asm volatile("mma.sync.aligned.m16n8k16.row.col.f32.f16.f16.f32 "
        "{%0,%1,%2,%3}, {%4,%5,%6,%7}, {%8,%9}, {%0,%1,%2,%3};"
        : "+f"(d[0]), "+f"(d[1]), "+f"(d[2]), "+f"(d[3])
        : "r"(a[0]), "r"(a[1]), "r"(a[2]), "r"(a[3]), "r"(b0), "r"(b1));
}
__device__ __forceinline__ int pperm(int o) {
    return 4 * ((o & 7) >> 1) + (((o >> 3) & 1) << 1) + (o & 1);
}

// ---------------- prep: fragment images ----------------
__global__ void prep_kernel(const float* __restrict__ Wih, const float* __restrict__ Whh,
                            const float* __restrict__ bih, const float* __restrict__ bhh,
                            const float* __restrict__ Wout) {
    int i = blockIdx.x * blockDim.x + threadIdx.x;
    if (i < EMB * G3) { int k = i / G3, gj = i % G3; g_Wih_t[i] = Wih[gj * EMB + k]; }
    if (i < G3) g_cbias[i] = bih[i] + (i < 2 * HID ? bhh[i] : 0.0f);
    if (i < G3 * HID) {
        int gj = i / HID, k = i % HID;
        uint16_t hb = __half_as_ushort(__float2half_rn(Whh[i]));
        int gate = gj >> 7, jr = gj & 127;
        int jc = jr >> 4, nt = (jr >> 3) & 1, nl = jr & 7;
        int kc = k >> 4, kk = k & 15;
        int breg = kk >> 3, q = (kk & 7) >> 1, hs = kk & 1;
        int T = nl * 4 + q, f = gate * 2 + nt;
        int u = ((jc * 8 + kc) * 32 + T) * 12 + f * 2 + breg;
        ((uint16_t*)g_Bf)[u * 2 + hs] = hb;
    }
    if (i < OUTD * HID) {
        int o = i / HID, k = i % HID;
        uint16_t hb = __half_as_ushort(__float2half_rn(Wout[i]));
        int f = o >> 3, nl = o & 7;
        int kc = k >> 4, kk = k & 15;
        int breg = kk >> 3, q = (kk & 7) >> 1, hs = kk & 1;
        int T = nl * 4 + q;
        int u = (kc * 32 + T) * 32 + f * 2 + breg;
        ((uint16_t*)g_Of)[u * 2 + hs] = hb;
    }
}

__global__ void table_kernel(const float* __restrict__ embed) {
    __shared__ float es[EMB];
    const int v = blockIdx.x, gj = threadIdx.x;
    if (gj < EMB) es[gj] = embed[v * EMB + gj];
    __syncthreads();
    float acc = 0.0f;
    #pragma unroll 8
    for (int k = 0; k < EMB; k++) acc = fmaf(es[k], g_Wih_t[k * G3 + gj], acc);
    const int gate = gj >> 7, rest = gj & 127, chunk = rest >> 4, o = rest & 15;
    g_tab[v * G3 + gate * 128 + chunk * 16 + pperm(o)] = acc + g_cbias[gj];
}

// ---------------- GRU: static-index pipelined loads + folded d-init + fast gates ----------------
#define GRU_SMEM (131072 + 512)
__global__ __launch_bounds__(128, 1) void gru_kernel(const int* __restrict__ x,
                                                     const float* __restrict__ bhh,
                                                     const float* __restrict__ bout,
                                                     float* __restrict__ out) {
    extern __shared__ uint32_t sm[];
    uint32_t* Bs = sm;                      // 24576 u32
    uint32_t* Os = sm + 24576;              // 8192 u32
    float* bns = (float*)(sm + 32768);      // 128 floats, permuted bhh_n
    const int tid = threadIdx.x;
    {
        uint4* d = (uint4*)sm;
        const uint4* s1 = (const uint4*)g_Bf;
        for (int i = tid; i < 6144; i += 128) d[i] = s1[i];
        const uint4* s2 = (const uint4*)g_Of;
        for (int i = tid; i < 2048; i += 128) d[6144 + i] = s2[i];
    }
    if (tid < 128) {
        int o = tid & 15, chunk = tid >> 4;
        bns[chunk * 16 + pperm(o)] = bhh[256 + tid];
    }
    __syncthreads();

    const int w = tid >> 5, T = tid & 31;
    const int g = T >> 2, a4 = (T & 3) * 4;
    const int rowA = blockIdx.x * 64 + w * 16 + g;
    const int rowB = rowA + 8;
    const float* __restrict__ tab = g_tab;

    uint32_t A[32], An[32];
    float hp[64];
    #pragma unroll
    for (int i = 0; i < 32; i++) A[i] = 0u;
    #pragma unroll
    for (int i = 0; i < 64; i++) hp[i] = 0.0f;

    int idxA = x[rowA * L_SZ], idxB = x[rowB * L_SZ];
    const float* tA = tab + (size_t)idxA * G3 + a4;
    const float* tB = tab + (size_t)idxB * G3 + a4;

    // preload chunk 0 of step 0
    float4 crA = __ldg((const float4*)(tA));
    float4 crB = __ldg((const float4*)(tB));
    float4 czA = __ldg((const float4*)(tA + 128));
    float4 czB = __ldg((const float4*)(tB + 128));
    float4 cnA = __ldg((const float4*)(tA + 256));
    float4 cnB = __ldg((const float4*)(tB + 256));

    #pragma unroll 1
    for (int t = 0; t < L_SZ; t++) {
        int idxA2 = idxA, idxB2 = idxB;
        if (t + 1 < L_SZ) {
            idxA2 = x[rowA * L_SZ + t + 1];
            idxB2 = x[rowB * L_SZ + t + 1];
        }
        #pragma unroll
        for (int jc = 0; jc < 8; jc++) {               // STATIC index — no spills
            float4 bn4 = *(const float4*)(bns + jc * 16 + a4);

            // accumulators pre-seeded with gate offsets
            float d[6][4] = {
                {crA.x, crA.y, crB.x, crB.y}, {crA.z, crA.w, crB.z, crB.w},
                {czA.x, czA.y, czB.x, czB.y}, {czA.z, czA.w, czB.z, czB.w},
                {bn4.x, bn4.y, bn4.x, bn4.y}, {bn4.z, bn4.w, bn4.z, bn4.w}
            };

            // prefetch next chunk's xg (static: jc+1, wrapping into next step)
            float4 nrA, nrB, nzA, nzB, nnA, nnB;
            if (jc < 7) {
                const int jn = (jc + 1) * 16;
                nrA = __ldg((const float4*)(tA + jn));
                nrB = __ldg((const float4*)(tB + jn));
                nzA = __ldg((const float4*)(tA + 128 + jn));
                nzB = __ldg((const float4*)(tB + 128 + jn));
                nnA = __ldg((const float4*)(tA + 256 + jn));
                nnB = __ldg((const float4*)(tB + 256 + jn));
            } else {
                tA = tab + (size_t)idxA2 * G3 + a4;
                tB = tab + (size_t)idxB2 * G3 + a4;
                nrA = __ldg((const float4*)(tA));
                nrB = __ldg((const float4*)(tB));
                nzA = __ldg((const float4*)(tA + 128));
                nzB = __ldg((const float4*)(tB + 128));
                nnA = __ldg((const float4*)(tA + 256));
                nnB = __ldg((const float4*)(tB + 256));
            }

            #pragma unroll
            for (int kc = 0; kc < 8; kc++) {
                const uint4* bp = (const uint4*)(Bs + ((jc * 8 + kc) * 32 + T) * 12);
                uint4 b0 = bp[0], b1 = bp[1], b2 = bp[2];
                hmma(d[0], &A[kc * 4], b0.x, b0.y);
                hmma(d[1], &A[kc * 4], b0.z, b0.w);
                hmma(d[2], &A[kc * 4], b1.x, b1.y);
                hmma(d[3], &A[kc * 4], b1.z, b1.w);
                hmma(d[4], &A[kc * 4], b2.x, b2.y);
                hmma(d[5], &A[kc * 4], b2.z, b2.w);
            }

            float xn[8] = {cnA.x, cnA.y, cnB.x, cnB.y, cnA.z, cnA.w, cnB.z, cnB.w};
            float hv[8];
            #pragma unroll
            for (int u = 0; u < 8; u++) {
                int nt = u >> 2, pos = u & 3;
                float r = fsig_fast(d[nt][pos]);
                float z = fsig_fast(d[2 + nt][pos]);
                float n = ftanh_fast(fmaf(r, d[4 + nt][pos], xn[u]));
                float h = fmaf(z, hp[jc * 8 + u] - n, n);
                hp[jc * 8 + u] = h;
                hv[u] = h;
            }
            An[jc * 4 + 0] = packh2(hv[0], hv[1]);
            An[jc * 4 + 1] = packh2(hv[2], hv[3]);
            An[jc * 4 + 2] = packh2(hv[4], hv[5]);
            An[jc * 4 + 3] = packh2(hv[6], hv[7]);

            crA = nrA; crB = nrB; czA = nzA; czB = nzB; cnA = nnA; cnB = nnB;
        }
        #pragma unroll
        for (int i = 0; i < 32; i++) A[i] = An[i];
        idxA = idxA2; idxB = idxB2;
    }

    // output projection: out = h @ Wout^T + bout
    float od[16][4];
    #pragma unroll
    for (int f = 0; f < 16; f++)
        #pragma unroll
        for (int p = 0; p < 4; p++) od[f][p] = 0.0f;
    #pragma unroll
    for (int kc = 0; kc < 8; kc++) {
        const uint4* op = (const uint4*)(Os + (kc * 32 + T) * 32);
        #pragma unroll
        for (int f2 = 0; f2 < 8; f2++) {
            uint4 v = op[f2];
            hmma(od[f2 * 2 + 0], &A[kc * 4], v.x, v.y);
            hmma(od[f2 * 2 + 1], &A[kc * 4], v.z, v.w);
        }
    }
    const int q2 = (T & 3) * 2;
    #pragma unroll
    for (int f = 0; f < 16; f++) {
        float2 bo = *(const float2*)(bout + f * 8 + q2);
        float2 oA = make_float2(od[f][0] + bo.x, od[f][1] + bo.y);
        float2 oB = make_float2(od[f][2] + bo.x, od[f][3] + bo.y);
        *(float2*)(out + (size_t)rowA * OUTD + f * 8 + q2) = oA;
        *(float2*)(out + (size_t)rowB * OUTD + f * 8 + q2) = oB;
    }
}

extern "C" void kernel_launch(void* const* d_in, const int* in_sizes, int n_in,
                              void* d_out, int out_size) {
    const int*   x     = (const int*)d_in[0];
    const float* embed = (const float*)d_in[1];
    const float* Wih   = (const float*)d_in[2];
    const float* Whh   = (const float*)d_in[3];
    const float* bih   = (const float*)d_in[4];
    const float* bhh   = (const float*)d_in[5];
    const float* Wout  = (const float*)d_in[6];
    const float* bout  = (const float*)d_in[7];
    float* out = (float*)d_out;

    static bool attr_done = false;
    if (!attr_done) {
        cudaFuncSetAttribute(gru_kernel, cudaFuncAttributeMaxDynamicSharedMemorySize, GRU_SMEM);
        attr_done = true;
    }

    prep_kernel<<<192, 256>>>(Wih, Whh, bih, bhh, Wout);
    table_kernel<<<NVAL, G3>>>(embed);
    gru_kernel<<<B_SZ / 64, 128, GRU_SMEM>>>(x, bhh, bout, out);
}